// round 12
// baseline (speedup 1.0000x reference)
#include <cuda_runtime.h>
#include <cuda_bf16.h>
#include <math.h>
#include <stdint.h>

#define BATCH 8
#define SEQ   1500
#define DMODEL 768
#define NHEAD 12
#define DHEAD 64
#define NTOK  (BATCH * SEQ)        // 12000
#define QSCALE 0.125f
#define NEG_BIG (-1e30f)
#define DD (DMODEL * DMODEL)

typedef unsigned long long ull;

// ---------------- packed f32x2 helpers (attention) ---------------------------
__device__ __forceinline__ ull dup2(float x) {
    ull r; asm("mov.b64 %0, {%1, %1};" : "=l"(r) : "f"(x)); return r;
}
__device__ __forceinline__ void fma2(ull& d, ull a, ull b) {
    asm("fma.rn.f32x2 %0, %1, %2, %0;" : "+l"(d) : "l"(a), "l"(b));
}
__device__ __forceinline__ void mul2(ull& d, ull a) {
    asm("mul.rn.f32x2 %0, %0, %1;" : "+l"(d) : "l"(a));
}
__device__ __forceinline__ float2 unpk(ull v) {
    float lo, hi; asm("mov.b64 {%0, %1}, %2;" : "=f"(lo), "=f"(hi) : "l"(v));
    return make_float2(lo, hi);
}

// ---------------- generic tensor-core helpers (arch-neutral PTX) -------------
__device__ __forceinline__ uint32_t smem_u32(const void* p) {
    uint32_t a;
    asm("{ .reg .u64 t; cvta.to.shared.u64 t, %1; cvt.u32.u64 %0, t; }" : "=r"(a) : "l"(p));
    return a;
}
__device__ __forceinline__ void ldm_x4(uint32_t& r0, uint32_t& r1,
                                       uint32_t& r2, uint32_t& r3, uint32_t addr) {
    asm volatile("ldmatrix.sync.aligned.m8n8.x4.shared.b16 {%0,%1,%2,%3}, [%4];"
                 : "=r"(r0), "=r"(r1), "=r"(r2), "=r"(r3) : "r"(addr));
}
__device__ __forceinline__ void mma_bf16(float* c, const uint32_t* a, const uint32_t* b) {
    asm volatile(
        "mma.sync.aligned.m16n8k16.row.col.f32.bf16.bf16.f32 "
        "{%0,%1,%2,%3}, {%4,%5,%6,%7}, {%8,%9}, {%0,%1,%2,%3};"
        : "+f"(c[0]), "+f"(c[1]), "+f"(c[2]), "+f"(c[3])
        : "r"(a[0]), "r"(a[1]), "r"(a[2]), "r"(a[3]), "r"(b[0]), "r"(b[1]));
}
__device__ __forceinline__ void cp16(uint32_t smem_addr, const void* gptr) {
    asm volatile("cp.async.cg.shared.global [%0], [%1], 16;"
                 :: "r"(smem_addr), "l"(gptr) : "memory");
}
__device__ __forceinline__ void cp_commit() {
    asm volatile("cp.async.commit_group;" ::: "memory");
}
template <int N>
__device__ __forceinline__ void cp_wait() {
    asm volatile("cp.async.wait_group %0;" :: "n"(N) : "memory");
}

// ---------------- scratch (device globals; no allocation) --------------------
__device__ float g_q[(size_t)BATCH * NHEAD * SEQ * DHEAD];   // [b,h,s,dh], pre-scaled
__device__ float g_k[(size_t)BATCH * NHEAD * SEQ * DHEAD];
__device__ float g_v[(size_t)BATCH * NHEAD * SEQ * DHEAD];
__device__ __nv_bfloat16 g_x_hi[(size_t)NTOK * DMODEL];
__device__ __nv_bfloat16 g_x_lo[(size_t)NTOK * DMODEL];
__device__ __nv_bfloat16 g_w_hi[(size_t)4 * DD];             // Wq,Wk,Wv,Wo
__device__ __nv_bfloat16 g_w_lo[(size_t)4 * DD];
__device__ __nv_bfloat16 g_c_hi[(size_t)NTOK * DMODEL];      // ctx split
__device__ __nv_bfloat16 g_c_lo[(size_t)NTOK * DMODEL];

// ===========================================================================
// Kernel 0: fp32 -> bf16 hi/lo split.  dst_sel: 0=x, 1..4 = Wq,Wk,Wv,Wo
// ===========================================================================
__global__ __launch_bounds__(256) void cvt_kernel(const float* __restrict__ src,
                                                  int dst_sel, int n)
{
    __nv_bfloat16 *hi, *lo;
    if (dst_sel == 0) { hi = g_x_hi; lo = g_x_lo; }
    else { hi = g_w_hi + (size_t)(dst_sel - 1) * DD; lo = g_w_lo + (size_t)(dst_sel - 1) * DD; }

    int i = (blockIdx.x * 256 + threadIdx.x) * 4;
    if (i >= n) return;
    float4 v = *(const float4*)(src + i);
    __nv_bfloat16 h0 = __float2bfloat16(v.x);
    __nv_bfloat16 h1 = __float2bfloat16(v.y);
    __nv_bfloat16 h2 = __float2bfloat16(v.z);
    __nv_bfloat16 h3 = __float2bfloat16(v.w);
    __nv_bfloat16 l0 = __float2bfloat16(v.x - __bfloat162float(h0));
    __nv_bfloat16 l1 = __float2bfloat16(v.y - __bfloat162float(h1));
    __nv_bfloat16 l2 = __float2bfloat16(v.z - __bfloat162float(h2));
    __nv_bfloat16 l3 = __float2bfloat16(v.w - __bfloat162float(h3));
    __nv_bfloat162* ph = (__nv_bfloat162*)(hi + i);
    __nv_bfloat162* pl = (__nv_bfloat162*)(lo + i);
    ph[0] = __nv_bfloat162(h0, h1); ph[1] = __nv_bfloat162(h2, h3);
    pl[0] = __nv_bfloat162(l0, l1); pl[1] = __nv_bfloat162(l2, l3);
}

// ===========================================================================
// HMMA GEMM: D[128 x 128] = A[128 x 768] @ B[128 x 768]^T, 3-term bf16 split.
//   mode 0 (qkv): A = x split, B = {Wq,Wk,Wv} split; epilogue -> g_q/g_k/g_v
//   mode 1 (out): A = ctx split, B = Wo split; epilogue -> d_out + bo
//   256 threads = 8 warps (2m x 4n); warp tile 64x32; mma m16n8k16 bf16.
//   K chunked by 64, cp.async double buffer: 2 x (4 tiles x 16 KB) = 128 KB.
// ===========================================================================
#define KC 64
#define NKC (DMODEL / KC)            // 12
#define TB 16384                     // one 128x64 bf16 tile
#define BUF (4 * TB)                 // Ah|Al|Bh|Bl
#define GEMM_SMEM (2 * BUF)

// swizzled byte offset inside a tile for (row 0..127, c8 = col/8, col in bf16)
__device__ __forceinline__ uint32_t swz(int row, int c8) {
    return (uint32_t)(row * 128 + ((c8 ^ (row & 7)) << 4));
}

__global__ __launch_bounds__(256) void gemm_mma_kernel(
    int mode,
    const float* __restrict__ bq, const float* __restrict__ bv,
    const float* __restrict__ bo, float* __restrict__ out)
{
    extern __shared__ char smem[];
    const uint32_t sb = smem_u32(smem);
    const int tid = threadIdx.x;
    const int wid = tid >> 5;
    const int lane = tid & 31;
    const int wm = wid & 1;          // 0..1  (64 rows each)
    const int wn = wid >> 1;         // 0..3  (32 cols each)

    const int mBase = blockIdx.y * 128;
    const int nFull = blockIdx.x * 128;
    int mat, oBase;
    const __nv_bfloat16 *Ah, *Al, *Bh, *Bl;
    if (mode == 0) {
        mat = nFull / DMODEL; oBase = nFull - mat * DMODEL;
        Ah = g_x_hi; Al = g_x_lo;
        Bh = g_w_hi + (size_t)mat * DD + (size_t)oBase * DMODEL;
        Bl = g_w_lo + (size_t)mat * DD + (size_t)oBase * DMODEL;
    } else {
        mat = 3; oBase = nFull;
        Ah = g_c_hi; Al = g_c_lo;
        Bh = g_w_hi + (size_t)3 * DD + (size_t)oBase * DMODEL;
        Bl = g_w_lo + (size_t)3 * DD + (size_t)oBase * DMODEL;
    }

    float acc[4][4][4];
#pragma unroll
    for (int mt = 0; mt < 4; mt++)
#pragma unroll
        for (int nt = 0; nt < 4; nt++)
#pragma unroll
            for (int e = 0; e < 4; e++) acc[mt][nt][e] = 0.f;

    // per-thread staging slots: u = i*256+tid -> (row = u>>3, c8 = u&7)
    // issue one chunk's cp.asyncs into buffer `buf`
    auto issue = [&](int c, int buf) {
        const int k0 = c * KC;
        const uint32_t base = sb + buf * BUF;
#pragma unroll
        for (int i = 0; i < 4; i++) {
            int u = i * 256 + tid;
            int row = u >> 3;
            int c8 = u & 7;
            uint32_t so = swz(row, c8);
            int ar = mBase + row; if (ar > NTOK - 1) ar = NTOK - 1;
            size_t aoff = (size_t)ar * DMODEL + k0 + c8 * 8;
            size_t boff = (size_t)row * DMODEL + k0 + c8 * 8;
            cp16(base + 0 * TB + so, Ah + aoff);
            cp16(base + 1 * TB + so, Al + aoff);
            cp16(base + 2 * TB + so, Bh + boff);
            cp16(base + 3 * TB + so, Bl + boff);
        }
        cp_commit();
    };

    issue(0, 0);

    // ldmatrix lane address components
    const int rA = (lane & 7) + ((lane >> 3) & 1) * 8;   // row within 16
    const int cA = (lane >> 4) & 1;                      // k-chunk select
    const int rB = (lane & 7) + ((lane >> 4) & 1) * 8;   // n within 16
    const int cB = (lane >> 3) & 1;

    for (int c = 0; c < NKC; c++) {
        if (c + 1 < NKC) { issue(c + 1, (c + 1) & 1); cp_wait<1>(); }
        else             { cp_wait<0>(); }
        __syncthreads();

        const uint32_t base = sb + (c & 1) * BUF;
        const uint32_t bAh = base, bAl = base + TB, bBh = base + 2 * TB, bBl = base + 3 * TB;

#pragma unroll
        for (int ks = 0; ks < 4; ks++) {
            const int kc8 = ks * 2;
            // B fragments: 4 n8-tiles, hi & lo
            uint32_t bh[4][2], bl[4][2];
#pragma unroll
            for (int half = 0; half < 2; half++) {
                int nrow = wn * 32 + half * 16 + rB;
                uint32_t off = swz(nrow, kc8 + cB);
                ldm_x4(bh[half * 2][0], bh[half * 2][1],
                       bh[half * 2 + 1][0], bh[half * 2 + 1][1], bBh + off);
                ldm_x4(bl[half * 2][0], bl[half * 2][1],
                       bl[half * 2 + 1][0], bl[half * 2 + 1][1], bBl + off);
            }
#pragma unroll
            for (int mt = 0; mt < 4; mt++) {
                int mrow = wm * 64 + mt * 16 + rA;
                uint32_t off = swz(mrow, kc8 + cA);
                uint32_t ah[4], al[4];
                ldm_x4(ah[0], ah[1], ah[2], ah[3], bAh + off);
                ldm_x4(al[0], al[1], al[2], al[3], bAl + off);
#pragma unroll
                for (int nt = 0; nt < 4; nt++) {
                    mma_bf16(acc[mt][nt], ah, bh[nt]);
                    mma_bf16(acc[mt][nt], ah, bl[nt]);
                    mma_bf16(acc[mt][nt], al, bh[nt]);
                }
            }
        }
        __syncthreads();
    }

    // ---- epilogue ----
    const int colW = oBase + wn * 32;                 // matrix-local col base of warp
#pragma unroll
    for (int nt = 0; nt < 4; nt++) {
        const int col = colW + nt * 8 + (lane & 3) * 2;
        float b0 = 0.f, b1 = 0.f;
        if (mode == 1)      { b0 = bo[col]; b1 = bo[col + 1]; }
        else if (mat == 0)  { b0 = bq[col]; b1 = bq[col + 1]; }
        else if (mat == 2)  { b0 = bv[col]; b1 = bv[col + 1]; }
        const float scl = (mode == 0 && mat == 0) ? QSCALE : 1.0f;
#pragma unroll
        for (int mt = 0; mt < 4; mt++) {
#pragma unroll
            for (int half = 0; half < 2; half++) {
                int t = mBase + wm * 64 + mt * 16 + (lane >> 2) + half * 8;
                if (t >= NTOK) continue;
                float v0 = (acc[mt][nt][half * 2 + 0] + b0) * scl;
                float v1 = (acc[mt][nt][half * 2 + 1] + b1) * scl;
                if (mode == 0) {
                    int b_ = t / SEQ;
                    int s_ = t - b_ * SEQ;
                    int hh = col >> 6, dh = col & 63;
                    float* dst = (mat == 0) ? g_q : (mat == 1) ? g_k : g_v;
                    size_t idx = (((size_t)b_ * NHEAD + hh) * SEQ + s_) * DHEAD + dh;
                    *(float2*)&dst[idx] = make_float2(v0, v1);
                } else {
                    *(float2*)&out[(size_t)t * DMODEL + col] = make_float2(v0, v1);
                }
            }
        }
    }
}

// ===========================================================================
// Flash attention, fp32 FMA2; epilogue emits ctx bf16 hi/lo.
// ===========================================================================
__global__ __launch_bounds__(256) void attn_kernel()
{
    __shared__ __align__(16) float Qt[64][64];   // [d][m]
    __shared__ __align__(16) float KP[64][64];   // [d][n] for K^T, then [m][j] for P
    __shared__ __align__(16) float Vs[64][64];   // [j][d]

    const int tid = threadIdx.x;
    const int tx = tid & 15;
    const int ty = tid >> 4;
    const int bh = blockIdx.y;
    const int b_ = bh / NHEAD;
    const int h_ = bh - b_ * NHEAD;
    const int q0 = blockIdx.x * 64;

    const float* Qg = g_q + (size_t)bh * SEQ * DHEAD;
    const float* Kg = g_k + (size_t)bh * SEQ * DHEAD;
    const float* Vg = g_v + (size_t)bh * SEQ * DHEAD;

    const int ldRow = tid >> 2;
    const int ldC0  = (tid & 3) * 4;

    {
        int qr = q0 + ldRow;
        const float* qp = Qg + (size_t)qr * DHEAD;
#pragma unroll
        for (int p = 0; p < 4; p++) {
            int c = ldC0 + p * 16;
            float4 qv = (qr < SEQ) ? *(const float4*)(qp + c) : make_float4(0, 0, 0, 0);
            Qt[c + 0][ldRow] = qv.x; Qt[c + 1][ldRow] = qv.y;
            Qt[c + 2][ldRow] = qv.z; Qt[c + 3][ldRow] = qv.w;
        }
    }

    ull O2[4][2];
#pragma unroll
    for (int i = 0; i < 4; i++) { O2[i][0] = 0ull; O2[i][1] = 0ull; }
    float mrow[4] = {NEG_BIG, NEG_BIG, NEG_BIG, NEG_BIG};
    float lrow[4] = {0.f, 0.f, 0.f, 0.f};

    const int NKT = (SEQ + 63) / 64;
    for (int kt = 0; kt < NKT; kt++) {
        const int kBase = kt * 64;

        float4 kfr[4], vfr[4];
        {
            int kr = kBase + ldRow;
            bool ok = kr < SEQ;
            const float* kp = Kg + (size_t)kr * DHEAD;
            const float* vp = Vg + (size_t)kr * DHEAD;
#pragma unroll
            for (int p = 0; p < 4; p++) {
                int c = ldC0 + p * 16;
                kfr[p] = ok ? *(const float4*)(kp + c) : make_float4(0, 0, 0, 0);
                vfr[p] = ok ? *(const float4*)(vp + c) : make_float4(0, 0, 0, 0);
            }
        }
        __syncthreads();
#pragma unroll
        for (int p = 0; p < 4; p++) {
            int c = ldC0 + p * 16;
            KP[c + 0][ldRow] = kfr[p].x; KP[c + 1][ldRow] = kfr[p].y;
            KP[c + 2][ldRow] = kfr[p].z; KP[c + 3][ldRow] = kfr[p].w;
            *(float4*)&Vs[ldRow][c] = vfr[p];
        }
        __syncthreads();

        ull s2[4][2];
#pragma unroll
        for (int i = 0; i < 4; i++) { s2[i][0] = 0ull; s2[i][1] = 0ull; }
#pragma unroll 16
        for (int d = 0; d < DHEAD; d++) {
            float4 af = *(const float4*)&Qt[d][ty * 4];
            ulonglong2 bu = *(const ulonglong2*)&KP[d][tx * 4];
            ull a0 = dup2(af.x), a1 = dup2(af.y), a2 = dup2(af.z), a3 = dup2(af.w);
            fma2(s2[0][0], a0, bu.x); fma2(s2[0][1], a0, bu.y);
            fma2(s2[1][0], a1, bu.x); fma2(s2[1][1], a1, bu.y);
            fma2(s2[2][0], a2, bu.x); fma2(s2[2][1], a2, bu.y);
            fma2(s2[3][0], a3, bu.x); fma2(s2[3][1], a3, bu.y);
        }

        float s[4][4];
#pragma unroll
        for (int i = 0; i < 4; i++) {
            float2 lo = unpk(s2[i][0]);
            float2 hi = unpk(s2[i][1]);
            s[i][0] = lo.x; s[i][1] = lo.y; s[i][2] = hi.x; s[i][3] = hi.y;
        }

#pragma unroll
        for (int j = 0; j < 4; j++) {
            if (kBase + tx * 4 + j >= SEQ) {
#pragma unroll
                for (int i = 0; i < 4; i++) s[i][j] = NEG_BIG;
            }
        }

#pragma unroll
        for (int i = 0; i < 4; i++) {
            float mx = fmaxf(fmaxf(s[i][0], s[i][1]), fmaxf(s[i][2], s[i][3]));
            mx = fmaxf(mx, __shfl_xor_sync(0xffffffffu, mx, 1));
            mx = fmaxf(mx, __shfl_xor_sync(0xffffffffu, mx, 2));
            mx = fmaxf(mx, __shfl_xor_sync(0xffffffffu, mx, 4));
            mx = fmaxf(mx, __shfl_xor_sync(0xffffffffu, mx, 8));
            float mnew = fmaxf(mrow[i], mx);
            float alpha = __expf(mrow[i] - mnew);
            mrow[i] = mnew;
            float rs = 0.f;
#pragma unroll
            for (int j = 0; j < 4; j++) {
                s[i][j] = __expf(s[i][j] - mnew);
                rs += s[i][j];
            }
            rs += __shfl_xor_sync(0xffffffffu, rs, 1);
            rs += __shfl_xor_sync(0xffffffffu, rs, 2);
            rs += __shfl_xor_sync(0xffffffffu, rs, 4);
            rs += __shfl_xor_sync(0xffffffffu, rs, 8);
            lrow[i] = lrow[i] * alpha + rs;
            ull ad = dup2(alpha);
            mul2(O2[i][0], ad); mul2(O2[i][1], ad);
        }

        __syncthreads();
#pragma unroll
        for (int i = 0; i < 4; i++) {
            *(float4*)&KP[ty * 4 + i][tx * 4] =
                make_float4(s[i][0], s[i][1], s[i][2], s[i][3]);
        }
        __syncthreads();

#pragma unroll 4
        for (int j = 0; j < 64; j += 4) {
            ulonglong2 v0 = *(const ulonglong2*)&Vs[j + 0][tx * 4];
            ulonglong2 v1 = *(const ulonglong2*)&Vs[j + 1][tx * 4];
            ulonglong2 v2 = *(const ulonglong2*)&Vs[j + 2][tx * 4];
            ulonglong2 v3 = *(const ulonglong2*)&Vs[j + 3][tx * 4];
#pragma unroll
            for (int i = 0; i < 4; i++) {
                float4 pf = *(const float4*)&KP[ty * 4 + i][j];
                ull p0 = dup2(pf.x), p1 = dup2(pf.y), p2 = dup2(pf.z), p3 = dup2(pf.w);
                fma2(O2[i][0], p0, v0.x); fma2(O2[i][1], p0, v0.y);
                fma2(O2[i][0], p1, v1.x); fma2(O2[i][1], p1, v1.y);
                fma2(O2[i][0], p2, v2.x); fma2(O2[i][1], p2, v2.y);
                fma2(O2[i][0], p3, v3.x); fma2(O2[i][1], p3, v3.y);
            }
        }
    }

    // ---- finalize: ctx -> bf16 hi/lo split ----
#pragma unroll
    for (int i = 0; i < 4; i++) {
        int qr = q0 + ty * 4 + i;
        if (qr >= SEQ) continue;
        float inv = 1.f / lrow[i];
        float2 lo2 = unpk(O2[i][0]);
        float2 hi2 = unpk(O2[i][1]);
        float vals[4] = {lo2.x * inv, lo2.y * inv, hi2.x * inv, hi2.y * inv};
        size_t idx = ((size_t)b_ * SEQ + qr) * DMODEL + h_ * DHEAD + tx * 4;
        __nv_bfloat16 h[4], l[4];
#pragma unroll
        for (int j = 0; j < 4; j++) {
            h[j] = __float2bfloat16(vals[j]);
            l[j] = __float2bfloat16(vals[j] - __bfloat162float(h[j]));
        }
        __nv_bfloat162* ph = (__nv_bfloat162*)&g_c_hi[idx];
        __nv_bfloat162* pl = (__nv_bfloat162*)&g_c_lo[idx];
        ph[0] = __nv_bfloat162(h[0], h[1]); ph[1] = __nv_bfloat162(h[2], h[3]);
        pl[0] = __nv_bfloat162(l[0], l[1]); pl[1] = __nv_bfloat162(l[2], l[3]);
    }
}

// ===========================================================================
extern "C" void kernel_launch(void* const* d_in, const int* in_sizes, int n_in,
                              void* d_out, int out_size)
{
    const float* x  = (const float*)d_in[0];
    const float* Wq = (const float*)d_in[1];
    const float* bq = (const float*)d_in[2];
    const float* Wk = (const float*)d_in[3];
    const float* Wv = (const float*)d_in[4];
    const float* bv = (const float*)d_in[5];
    const float* Wo = (const float*)d_in[6];
    const float* bo = (const float*)d_in[7];
    float* out = (float*)d_out;

    cudaFuncSetAttribute(gemm_mma_kernel,
                         cudaFuncAttributeMaxDynamicSharedMemorySize, GEMM_SMEM);

    // split inputs to bf16 hi/lo
    cvt_kernel<<<(NTOK * DMODEL) / 1024, 256>>>(x, 0, NTOK * DMODEL);
    cvt_kernel<<<DD / 1024, 256>>>(Wq, 1, DD);
    cvt_kernel<<<DD / 1024, 256>>>(Wk, 2, DD);
    cvt_kernel<<<DD / 1024, 256>>>(Wv, 3, DD);
    cvt_kernel<<<DD / 1024, 256>>>(Wo, 4, DD);

    // QKV projection on tensor cores (HMMA)
    dim3 gQKV(3 * DMODEL / 128, (NTOK + 127) / 128);   // (18, 94)
    gemm_mma_kernel<<<gQKV, 256, GEMM_SMEM>>>(0, bq, bv, bo, out);

    // flash attention (writes ctx split)
    dim3 gAtt((SEQ + 63) / 64, BATCH * NHEAD);          // (24, 96)
    attn_kernel<<<gAtt, 256>>>();

    // output projection on tensor cores (HMMA)
    dim3 gOut(DMODEL / 128, (NTOK + 127) / 128);        // (6, 94)
    gemm_mma_kernel<<<gOut, 256, GEMM_SMEM>>>(1, bq, bv, bo, out);
}

// round 14
// speedup vs baseline: 1.0009x; 1.0009x over previous
#include <cuda_runtime.h>
#include <cuda_bf16.h>
#include <math.h>
#include <stdint.h>

#define BATCH 8
#define SEQ   1500
#define DMODEL 768
#define NHEAD 12
#define DHEAD 64
#define NTOK  (BATCH * SEQ)        // 12000
#define QSCALE 0.125f
#define NEG_BIG (-1e30f)
#define DD (DMODEL * DMODEL)

typedef unsigned long long ull;

// ---------------- packed f32x2 helpers (attention) ---------------------------
__device__ __forceinline__ ull dup2(float x) {
    ull r; asm("mov.b64 %0, {%1, %1};" : "=l"(r) : "f"(x)); return r;
}
__device__ __forceinline__ void fma2(ull& d, ull a, ull b) {
    asm("fma.rn.f32x2 %0, %1, %2, %0;" : "+l"(d) : "l"(a), "l"(b));
}
__device__ __forceinline__ void mul2(ull& d, ull a) {
    asm("mul.rn.f32x2 %0, %0, %1;" : "+l"(d) : "l"(a));
}
__device__ __forceinline__ float2 unpk(ull v) {
    float lo, hi; asm("mov.b64 {%0, %1}, %2;" : "=f"(lo), "=f"(hi) : "l"(v));
    return make_float2(lo, hi);
}

// ---------------- generic tensor-core helpers (arch-neutral PTX) -------------
__device__ __forceinline__ uint32_t smem_u32(const void* p) {
    uint32_t a;
    asm("{ .reg .u64 t; cvta.to.shared.u64 t, %1; cvt.u32.u64 %0, t; }" : "=r"(a) : "l"(p));
    return a;
}
__device__ __forceinline__ void ldm_x4(uint32_t& r0, uint32_t& r1,
                                       uint32_t& r2, uint32_t& r3, uint32_t addr) {
    asm volatile("ldmatrix.sync.aligned.m8n8.x4.shared.b16 {%0,%1,%2,%3}, [%4];"
                 : "=r"(r0), "=r"(r1), "=r"(r2), "=r"(r3) : "r"(addr));
}
__device__ __forceinline__ void mma_bf16(float* c, const uint32_t* a, const uint32_t* b) {
    asm volatile(
        "mma.sync.aligned.m16n8k16.row.col.f32.bf16.bf16.f32 "
        "{%0,%1,%2,%3}, {%4,%5,%6,%7}, {%8,%9}, {%0,%1,%2,%3};"
        : "+f"(c[0]), "+f"(c[1]), "+f"(c[2]), "+f"(c[3])
        : "r"(a[0]), "r"(a[1]), "r"(a[2]), "r"(a[3]), "r"(b[0]), "r"(b[1]));
}
__device__ __forceinline__ void cp16(uint32_t smem_addr, const void* gptr) {
    asm volatile("cp.async.cg.shared.global [%0], [%1], 16;"
                 :: "r"(smem_addr), "l"(gptr) : "memory");
}
__device__ __forceinline__ void cp_commit() {
    asm volatile("cp.async.commit_group;" ::: "memory");
}
template <int N>
__device__ __forceinline__ void cp_wait() {
    asm volatile("cp.async.wait_group %0;" :: "n"(N) : "memory");
}

// ---------------- scratch (device globals; no allocation) --------------------
__device__ float g_q[(size_t)BATCH * NHEAD * SEQ * DHEAD];   // [b,h,s,dh], pre-scaled
__device__ float g_k[(size_t)BATCH * NHEAD * SEQ * DHEAD];
__device__ float g_v[(size_t)BATCH * NHEAD * SEQ * DHEAD];
__device__ __nv_bfloat16 g_x_hi[(size_t)NTOK * DMODEL];
__device__ __nv_bfloat16 g_x_lo[(size_t)NTOK * DMODEL];
__device__ __nv_bfloat16 g_w_hi[(size_t)4 * DD];             // Wq,Wk,Wv,Wo
__device__ __nv_bfloat16 g_w_lo[(size_t)4 * DD];
__device__ __nv_bfloat16 g_c_hi[(size_t)NTOK * DMODEL];      // ctx split
__device__ __nv_bfloat16 g_c_lo[(size_t)NTOK * DMODEL];

// ===========================================================================
// Kernel 0: fp32 -> bf16 hi/lo split.  dst_sel: 0=x, 1..4 = Wq,Wk,Wv,Wo
// ===========================================================================
__global__ __launch_bounds__(256) void cvt_kernel(const float* __restrict__ src,
                                                  int dst_sel, int n)
{
    __nv_bfloat16 *hi, *lo;
    if (dst_sel == 0) { hi = g_x_hi; lo = g_x_lo; }
    else { hi = g_w_hi + (size_t)(dst_sel - 1) * DD; lo = g_w_lo + (size_t)(dst_sel - 1) * DD; }

    int i = (blockIdx.x * 256 + threadIdx.x) * 4;
    if (i >= n) return;
    float4 v = *(const float4*)(src + i);
    __nv_bfloat16 h0 = __float2bfloat16(v.x);
    __nv_bfloat16 h1 = __float2bfloat16(v.y);
    __nv_bfloat16 h2 = __float2bfloat16(v.z);
    __nv_bfloat16 h3 = __float2bfloat16(v.w);
    __nv_bfloat16 l0 = __float2bfloat16(v.x - __bfloat162float(h0));
    __nv_bfloat16 l1 = __float2bfloat16(v.y - __bfloat162float(h1));
    __nv_bfloat16 l2 = __float2bfloat16(v.z - __bfloat162float(h2));
    __nv_bfloat16 l3 = __float2bfloat16(v.w - __bfloat162float(h3));
    __nv_bfloat162* ph = (__nv_bfloat162*)(hi + i);
    __nv_bfloat162* pl = (__nv_bfloat162*)(lo + i);
    ph[0] = __nv_bfloat162(h0, h1); ph[1] = __nv_bfloat162(h2, h3);
    pl[0] = __nv_bfloat162(l0, l1); pl[1] = __nv_bfloat162(l2, l3);
}

// ===========================================================================
// HMMA GEMM: D[128 x 128] = A[128 x 768] @ B[128 x 768]^T, 3-term bf16 split.
//   mode 0 (qkv): A = x split, B = {Wq,Wk,Wv} split; epilogue -> g_q/g_k/g_v
//   mode 1 (out): A = ctx split, B = Wo split; epilogue -> d_out + bo
//   256 threads = 8 warps (2m x 4n); warp tile 64x32; mma m16n8k16 bf16.
//   K chunked by 64, cp.async double buffer: 2 x (4 tiles x 16 KB) = 128 KB.
// ===========================================================================
#define KC 64
#define NKC (DMODEL / KC)            // 12
#define TB 16384                     // one 128x64 bf16 tile
#define BUF (4 * TB)                 // Ah|Al|Bh|Bl
#define GEMM_SMEM (2 * BUF)

// swizzled byte offset inside a tile for (row 0..127, c8 = col/8, col in bf16)
__device__ __forceinline__ uint32_t swz(int row, int c8) {
    return (uint32_t)(row * 128 + ((c8 ^ (row & 7)) << 4));
}

__global__ __launch_bounds__(256) void gemm_mma_kernel(
    int mode,
    const float* __restrict__ bq, const float* __restrict__ bv,
    const float* __restrict__ bo, float* __restrict__ out)
{
    extern __shared__ char smem[];
    const uint32_t sb = smem_u32(smem);
    const int tid = threadIdx.x;
    const int wid = tid >> 5;
    const int lane = tid & 31;
    const int wm = wid & 1;          // 0..1  (64 rows each)
    const int wn = wid >> 1;         // 0..3  (32 cols each)

    const int mBase = blockIdx.y * 128;
    const int nFull = blockIdx.x * 128;
    int mat, oBase;
    const __nv_bfloat16 *Ah, *Al, *Bh, *Bl;
    if (mode == 0) {
        mat = nFull / DMODEL; oBase = nFull - mat * DMODEL;
        Ah = g_x_hi; Al = g_x_lo;
        Bh = g_w_hi + (size_t)mat * DD + (size_t)oBase * DMODEL;
        Bl = g_w_lo + (size_t)mat * DD + (size_t)oBase * DMODEL;
    } else {
        mat = 3; oBase = nFull;
        Ah = g_c_hi; Al = g_c_lo;
        Bh = g_w_hi + (size_t)3 * DD + (size_t)oBase * DMODEL;
        Bl = g_w_lo + (size_t)3 * DD + (size_t)oBase * DMODEL;
    }

    float acc[4][4][4];
#pragma unroll
    for (int mt = 0; mt < 4; mt++)
#pragma unroll
        for (int nt = 0; nt < 4; nt++)
#pragma unroll
            for (int e = 0; e < 4; e++) acc[mt][nt][e] = 0.f;

    // per-thread staging slots: u = i*256+tid -> (row = u>>3, c8 = u&7)
    // issue one chunk's cp.asyncs into buffer `buf`
    auto issue = [&](int c, int buf) {
        const int k0 = c * KC;
        const uint32_t base = sb + buf * BUF;
#pragma unroll
        for (int i = 0; i < 4; i++) {
            int u = i * 256 + tid;
            int row = u >> 3;
            int c8 = u & 7;
            uint32_t so = swz(row, c8);
            int ar = mBase + row; if (ar > NTOK - 1) ar = NTOK - 1;
            size_t aoff = (size_t)ar * DMODEL + k0 + c8 * 8;
            size_t boff = (size_t)row * DMODEL + k0 + c8 * 8;
            cp16(base + 0 * TB + so, Ah + aoff);
            cp16(base + 1 * TB + so, Al + aoff);
            cp16(base + 2 * TB + so, Bh + boff);
            cp16(base + 3 * TB + so, Bl + boff);
        }
        cp_commit();
    };

    issue(0, 0);

    // ldmatrix lane address components
    const int rA = (lane & 7) + ((lane >> 3) & 1) * 8;   // row within 16
    const int cA = (lane >> 4) & 1;                      // k-chunk select
    const int rB = (lane & 7) + ((lane >> 4) & 1) * 8;   // n within 16
    const int cB = (lane >> 3) & 1;

    for (int c = 0; c < NKC; c++) {
        if (c + 1 < NKC) { issue(c + 1, (c + 1) & 1); cp_wait<1>(); }
        else             { cp_wait<0>(); }
        __syncthreads();

        const uint32_t base = sb + (c & 1) * BUF;
        const uint32_t bAh = base, bAl = base + TB, bBh = base + 2 * TB, bBl = base + 3 * TB;

#pragma unroll
        for (int ks = 0; ks < 4; ks++) {
            const int kc8 = ks * 2;
            // B fragments: 4 n8-tiles, hi & lo
            uint32_t bh[4][2], bl[4][2];
#pragma unroll
            for (int half = 0; half < 2; half++) {
                int nrow = wn * 32 + half * 16 + rB;
                uint32_t off = swz(nrow, kc8 + cB);
                ldm_x4(bh[half * 2][0], bh[half * 2][1],
                       bh[half * 2 + 1][0], bh[half * 2 + 1][1], bBh + off);
                ldm_x4(bl[half * 2][0], bl[half * 2][1],
                       bl[half * 2 + 1][0], bl[half * 2 + 1][1], bBl + off);
            }
#pragma unroll
            for (int mt = 0; mt < 4; mt++) {
                int mrow = wm * 64 + mt * 16 + rA;
                uint32_t off = swz(mrow, kc8 + cA);
                uint32_t ah[4], al[4];
                ldm_x4(ah[0], ah[1], ah[2], ah[3], bAh + off);
                ldm_x4(al[0], al[1], al[2], al[3], bAl + off);
#pragma unroll
                for (int nt = 0; nt < 4; nt++) {
                    mma_bf16(acc[mt][nt], ah, bh[nt]);
                    mma_bf16(acc[mt][nt], ah, bl[nt]);
                    mma_bf16(acc[mt][nt], al, bh[nt]);
                }
            }
        }
        __syncthreads();
    }

    // ---- epilogue ----
    const int colW = oBase + wn * 32;                 // matrix-local col base of warp
#pragma unroll
    for (int nt = 0; nt < 4; nt++) {
        const int col = colW + nt * 8 + (lane & 3) * 2;
        float b0 = 0.f, b1 = 0.f;
        if (mode == 1)      { b0 = bo[col]; b1 = bo[col + 1]; }
        else if (mat == 0)  { b0 = bq[col]; b1 = bq[col + 1]; }
        else if (mat == 2)  { b0 = bv[col]; b1 = bv[col + 1]; }
        const float scl = (mode == 0 && mat == 0) ? QSCALE : 1.0f;
#pragma unroll
        for (int mt = 0; mt < 4; mt++) {
#pragma unroll
            for (int half = 0; half < 2; half++) {
                int t = mBase + wm * 64 + mt * 16 + (lane >> 2) + half * 8;
                if (t >= NTOK) continue;
                float v0 = (acc[mt][nt][half * 2 + 0] + b0) * scl;
                float v1 = (acc[mt][nt][half * 2 + 1] + b1) * scl;
                if (mode == 0) {
                    int b_ = t / SEQ;
                    int s_ = t - b_ * SEQ;
                    int hh = col >> 6, dh = col & 63;
                    float* dst = (mat == 0) ? g_q : (mat == 1) ? g_k : g_v;
                    size_t idx = (((size_t)b_ * NHEAD + hh) * SEQ + s_) * DHEAD + dh;
                    *(float2*)&dst[idx] = make_float2(v0, v1);
                } else {
                    *(float2*)&out[(size_t)t * DMODEL + col] = make_float2(v0, v1);
                }
            }
        }
    }
}

// ===========================================================================
// Flash attention, fp32 FMA2; epilogue emits ctx bf16 hi/lo.
// ===========================================================================
__global__ __launch_bounds__(256) void attn_kernel()
{
    __shared__ __align__(16) float Qt[64][64];   // [d][m]
    __shared__ __align__(16) float KP[64][64];   // [d][n] for K^T, then [m][j] for P
    __shared__ __align__(16) float Vs[64][64];   // [j][d]

    const int tid = threadIdx.x;
    const int tx = tid & 15;
    const int ty = tid >> 4;
    const int bh = blockIdx.y;
    const int b_ = bh / NHEAD;
    const int h_ = bh - b_ * NHEAD;
    const int q0 = blockIdx.x * 64;

    const float* Qg = g_q + (size_t)bh * SEQ * DHEAD;
    const float* Kg = g_k + (size_t)bh * SEQ * DHEAD;
    const float* Vg = g_v + (size_t)bh * SEQ * DHEAD;

    const int ldRow = tid >> 2;
    const int ldC0  = (tid & 3) * 4;

    {
        int qr = q0 + ldRow;
        const float* qp = Qg + (size_t)qr * DHEAD;
#pragma unroll
        for (int p = 0; p < 4; p++) {
            int c = ldC0 + p * 16;
            float4 qv = (qr < SEQ) ? *(const float4*)(qp + c) : make_float4(0, 0, 0, 0);
            Qt[c + 0][ldRow] = qv.x; Qt[c + 1][ldRow] = qv.y;
            Qt[c + 2][ldRow] = qv.z; Qt[c + 3][ldRow] = qv.w;
        }
    }

    ull O2[4][2];
#pragma unroll
    for (int i = 0; i < 4; i++) { O2[i][0] = 0ull; O2[i][1] = 0ull; }
    float mrow[4] = {NEG_BIG, NEG_BIG, NEG_BIG, NEG_BIG};
    float lrow[4] = {0.f, 0.f, 0.f, 0.f};

    const int NKT = (SEQ + 63) / 64;
    for (int kt = 0; kt < NKT; kt++) {
        const int kBase = kt * 64;

        float4 kfr[4], vfr[4];
        {
            int kr = kBase + ldRow;
            bool ok = kr < SEQ;
            const float* kp = Kg + (size_t)kr * DHEAD;
            const float* vp = Vg + (size_t)kr * DHEAD;
#pragma unroll
            for (int p = 0; p < 4; p++) {
                int c = ldC0 + p * 16;
                kfr[p] = ok ? *(const float4*)(kp + c) : make_float4(0, 0, 0, 0);
                vfr[p] = ok ? *(const float4*)(vp + c) : make_float4(0, 0, 0, 0);
            }
        }
        __syncthreads();
#pragma unroll
        for (int p = 0; p < 4; p++) {
            int c = ldC0 + p * 16;
            KP[c + 0][ldRow] = kfr[p].x; KP[c + 1][ldRow] = kfr[p].y;
            KP[c + 2][ldRow] = kfr[p].z; KP[c + 3][ldRow] = kfr[p].w;
            *(float4*)&Vs[ldRow][c] = vfr[p];
        }
        __syncthreads();

        ull s2[4][2];
#pragma unroll
        for (int i = 0; i < 4; i++) { s2[i][0] = 0ull; s2[i][1] = 0ull; }
#pragma unroll 16
        for (int d = 0; d < DHEAD; d++) {
            float4 af = *(const float4*)&Qt[d][ty * 4];
            ulonglong2 bu = *(const ulonglong2*)&KP[d][tx * 4];
            ull a0 = dup2(af.x), a1 = dup2(af.y), a2 = dup2(af.z), a3 = dup2(af.w);
            fma2(s2[0][0], a0, bu.x); fma2(s2[0][1], a0, bu.y);
            fma2(s2[1][0], a1, bu.x); fma2(s2[1][1], a1, bu.y);
            fma2(s2[2][0], a2, bu.x); fma2(s2[2][1], a2, bu.y);
            fma2(s2[3][0], a3, bu.x); fma2(s2[3][1], a3, bu.y);
        }

        float s[4][4];
#pragma unroll
        for (int i = 0; i < 4; i++) {
            float2 lo = unpk(s2[i][0]);
            float2 hi = unpk(s2[i][1]);
            s[i][0] = lo.x; s[i][1] = lo.y; s[i][2] = hi.x; s[i][3] = hi.y;
        }

#pragma unroll
        for (int j = 0; j < 4; j++) {
            if (kBase + tx * 4 + j >= SEQ) {
#pragma unroll
                for (int i = 0; i < 4; i++) s[i][j] = NEG_BIG;
            }
        }

#pragma unroll
        for (int i = 0; i < 4; i++) {
            float mx = fmaxf(fmaxf(s[i][0], s[i][1]), fmaxf(s[i][2], s[i][3]));
            mx = fmaxf(mx, __shfl_xor_sync(0xffffffffu, mx, 1));
            mx = fmaxf(mx, __shfl_xor_sync(0xffffffffu, mx, 2));
            mx = fmaxf(mx, __shfl_xor_sync(0xffffffffu, mx, 4));
            mx = fmaxf(mx, __shfl_xor_sync(0xffffffffu, mx, 8));
            float mnew = fmaxf(mrow[i], mx);
            float alpha = __expf(mrow[i] - mnew);
            mrow[i] = mnew;
            float rs = 0.f;
#pragma unroll
            for (int j = 0; j < 4; j++) {
                s[i][j] = __expf(s[i][j] - mnew);
                rs += s[i][j];
            }
            rs += __shfl_xor_sync(0xffffffffu, rs, 1);
            rs += __shfl_xor_sync(0xffffffffu, rs, 2);
            rs += __shfl_xor_sync(0xffffffffu, rs, 4);
            rs += __shfl_xor_sync(0xffffffffu, rs, 8);
            lrow[i] = lrow[i] * alpha + rs;
            ull ad = dup2(alpha);
            mul2(O2[i][0], ad); mul2(O2[i][1], ad);
        }

        __syncthreads();
#pragma unroll
        for (int i = 0; i < 4; i++) {
            *(float4*)&KP[ty * 4 + i][tx * 4] =
                make_float4(s[i][0], s[i][1], s[i][2], s[i][3]);
        }
        __syncthreads();

#pragma unroll 4
        for (int j = 0; j < 64; j += 4) {
            ulonglong2 v0 = *(const ulonglong2*)&Vs[j + 0][tx * 4];
            ulonglong2 v1 = *(const ulonglong2*)&Vs[j + 1][tx * 4];
            ulonglong2 v2 = *(const ulonglong2*)&Vs[j + 2][tx * 4];
            ulonglong2 v3 = *(const ulonglong2*)&Vs[j + 3][tx * 4];
#pragma unroll
            for (int i = 0; i < 4; i++) {
                float4 pf = *(const float4*)&KP[ty * 4 + i][j];
                ull p0 = dup2(pf.x), p1 = dup2(pf.y), p2 = dup2(pf.z), p3 = dup2(pf.w);
                fma2(O2[i][0], p0, v0.x); fma2(O2[i][1], p0, v0.y);
                fma2(O2[i][0], p1, v1.x); fma2(O2[i][1], p1, v1.y);
                fma2(O2[i][0], p2, v2.x); fma2(O2[i][1], p2, v2.y);
                fma2(O2[i][0], p3, v3.x); fma2(O2[i][1], p3, v3.y);
            }
        }
    }

    // ---- finalize: ctx -> bf16 hi/lo split ----
#pragma unroll
    for (int i = 0; i < 4; i++) {
        int qr = q0 + ty * 4 + i;
        if (qr >= SEQ) continue;
        float inv = 1.f / lrow[i];
        float2 lo2 = unpk(O2[i][0]);
        float2 hi2 = unpk(O2[i][1]);
        float vals[4] = {lo2.x * inv, lo2.y * inv, hi2.x * inv, hi2.y * inv};
        size_t idx = ((size_t)b_ * SEQ + qr) * DMODEL + h_ * DHEAD + tx * 4;
        __nv_bfloat16 h[4], l[4];
#pragma unroll
        for (int j = 0; j < 4; j++) {
            h[j] = __float2bfloat16(vals[j]);
            l[j] = __float2bfloat16(vals[j] - __bfloat162float(h[j]));
        }
        __nv_bfloat162* ph = (__nv_bfloat162*)&g_c_hi[idx];
        __nv_bfloat162* pl = (__nv_bfloat162*)&g_c_lo[idx];
        ph[0] = __nv_bfloat162(h[0], h[1]); ph[1] = __nv_bfloat162(h[2], h[3]);
        pl[0] = __nv_bfloat162(l[0], l[1]); pl[1] = __nv_bfloat162(l[2], l[3]);
    }
}

// ===========================================================================
extern "C" void kernel_launch(void* const* d_in, const int* in_sizes, int n_in,
                              void* d_out, int out_size)
{
    const float* x  = (const float*)d_in[0];
    const float* Wq = (const float*)d_in[1];
    const float* bq = (const float*)d_in[2];
    const float* Wk = (const float*)d_in[3];
    const float* Wv = (const float*)d_in[4];
    const float* bv = (const float*)d_in[5];
    const float* Wo = (const float*)d_in[6];
    const float* bo = (const float*)d_in[7];
    float* out = (float*)d_out;

    cudaFuncSetAttribute(gemm_mma_kernel,
                         cudaFuncAttributeMaxDynamicSharedMemorySize, GEMM_SMEM);

    // split inputs to bf16 hi/lo
    cvt_kernel<<<(NTOK * DMODEL) / 1024, 256>>>(x, 0, NTOK * DMODEL);
    cvt_kernel<<<DD / 1024, 256>>>(Wq, 1, DD);
    cvt_kernel<<<DD / 1024, 256>>>(Wk, 2, DD);
    cvt_kernel<<<DD / 1024, 256>>>(Wv, 3, DD);
    cvt_kernel<<<DD / 1024, 256>>>(Wo, 4, DD);

    // QKV projection on tensor cores (HMMA)
    dim3 gQKV(3 * DMODEL / 128, (NTOK + 127) / 128);   // (18, 94)
    gemm_mma_kernel<<<gQKV, 256, GEMM_SMEM>>>(0, bq, bv, bo, out);

    // flash attention (writes ctx split)
    dim3 gAtt((SEQ + 63) / 64, BATCH * NHEAD);          // (24, 96)
    attn_kernel<<<gAtt, 256>>>();

    // output projection on tensor cores (HMMA)
    dim3 gOut(DMODEL / 128, (NTOK + 127) / 128);        // (6, 94)
    gemm_mma_kernel<<<gOut, 256, GEMM_SMEM>>>(1, bq, bv, bo, out);
}

// round 15
// speedup vs baseline: 1.0010x; 1.0002x over previous
#include <cuda_runtime.h>
#include <cuda_bf16.h>
#include <math.h>
#include <stdint.h>

#define BATCH 8
#define SEQ   1500
#define DMODEL 768
#define NHEAD 12
#define DHEAD 64
#define NTOK  (BATCH * SEQ)        // 12000
#define QSCALE 0.125f
#define NEG_BIG (-1e30f)
#define DD (DMODEL * DMODEL)

typedef unsigned long long ull;

// ---------------- packed f32x2 helpers (attention) ---------------------------
__device__ __forceinline__ ull dup2(float x) {
    ull r; asm("mov.b64 %0, {%1, %1};" : "=l"(r) : "f"(x)); return r;
}
__device__ __forceinline__ void fma2(ull& d, ull a, ull b) {
    asm("fma.rn.f32x2 %0, %1, %2, %0;" : "+l"(d) : "l"(a), "l"(b));
}
__device__ __forceinline__ void mul2(ull& d, ull a) {
    asm("mul.rn.f32x2 %0, %0, %1;" : "+l"(d) : "l"(a));
}
__device__ __forceinline__ float2 unpk(ull v) {
    float lo, hi; asm("mov.b64 {%0, %1}, %2;" : "=f"(lo), "=f"(hi) : "l"(v));
    return make_float2(lo, hi);
}

// ---------------- generic tensor-core helpers (arch-neutral PTX) -------------
__device__ __forceinline__ uint32_t smem_u32(const void* p) {
    uint32_t a;
    asm("{ .reg .u64 t; cvta.to.shared.u64 t, %1; cvt.u32.u64 %0, t; }" : "=r"(a) : "l"(p));
    return a;
}
__device__ __forceinline__ void ldm_x4(uint32_t& r0, uint32_t& r1,
                                       uint32_t& r2, uint32_t& r3, uint32_t addr) {
    asm volatile("ldmatrix.sync.aligned.m8n8.x4.shared.b16 {%0,%1,%2,%3}, [%4];"
                 : "=r"(r0), "=r"(r1), "=r"(r2), "=r"(r3) : "r"(addr));
}
__device__ __forceinline__ void mma_bf16(float* c, const uint32_t* a, const uint32_t* b) {
    asm volatile(
        "mma.sync.aligned.m16n8k16.row.col.f32.bf16.bf16.f32 "
        "{%0,%1,%2,%3}, {%4,%5,%6,%7}, {%8,%9}, {%0,%1,%2,%3};"
        : "+f"(c[0]), "+f"(c[1]), "+f"(c[2]), "+f"(c[3])
        : "r"(a[0]), "r"(a[1]), "r"(a[2]), "r"(a[3]), "r"(b[0]), "r"(b[1]));
}
__device__ __forceinline__ void cp16(uint32_t smem_addr, const void* gptr) {
    asm volatile("cp.async.cg.shared.global [%0], [%1], 16;"
                 :: "r"(smem_addr), "l"(gptr) : "memory");
}
__device__ __forceinline__ void cp_commit() {
    asm volatile("cp.async.commit_group;" ::: "memory");
}
template <int N>
__device__ __forceinline__ void cp_wait() {
    asm volatile("cp.async.wait_group %0;" :: "n"(N) : "memory");
}

// ---------------- scratch (device globals; no allocation) --------------------
__device__ float g_q[(size_t)BATCH * NHEAD * SEQ * DHEAD];   // [b,h,s,dh], pre-scaled
__device__ float g_k[(size_t)BATCH * NHEAD * SEQ * DHEAD];
__device__ float g_v[(size_t)BATCH * NHEAD * SEQ * DHEAD];
__device__ __nv_bfloat16 g_x_hi[(size_t)NTOK * DMODEL];
__device__ __nv_bfloat16 g_x_lo[(size_t)NTOK * DMODEL];
__device__ __nv_bfloat16 g_w_hi[(size_t)4 * DD];             // Wq,Wk,Wv,Wo
__device__ __nv_bfloat16 g_w_lo[(size_t)4 * DD];
__device__ __nv_bfloat16 g_c_hi[(size_t)NTOK * DMODEL];      // ctx split
__device__ __nv_bfloat16 g_c_lo[(size_t)NTOK * DMODEL];

// ===========================================================================
// Kernel 0: fp32 -> bf16 hi/lo split.  dst_sel: 0=x, 1..4 = Wq,Wk,Wv,Wo
// ===========================================================================
__global__ __launch_bounds__(256) void cvt_kernel(const float* __restrict__ src,
                                                  int dst_sel, int n)
{
    __nv_bfloat16 *hi, *lo;
    if (dst_sel == 0) { hi = g_x_hi; lo = g_x_lo; }
    else { hi = g_w_hi + (size_t)(dst_sel - 1) * DD; lo = g_w_lo + (size_t)(dst_sel - 1) * DD; }

    int i = (blockIdx.x * 256 + threadIdx.x) * 4;
    if (i >= n) return;
    float4 v = *(const float4*)(src + i);
    __nv_bfloat16 h0 = __float2bfloat16(v.x);
    __nv_bfloat16 h1 = __float2bfloat16(v.y);
    __nv_bfloat16 h2 = __float2bfloat16(v.z);
    __nv_bfloat16 h3 = __float2bfloat16(v.w);
    __nv_bfloat16 l0 = __float2bfloat16(v.x - __bfloat162float(h0));
    __nv_bfloat16 l1 = __float2bfloat16(v.y - __bfloat162float(h1));
    __nv_bfloat16 l2 = __float2bfloat16(v.z - __bfloat162float(h2));
    __nv_bfloat16 l3 = __float2bfloat16(v.w - __bfloat162float(h3));
    __nv_bfloat162* ph = (__nv_bfloat162*)(hi + i);
    __nv_bfloat162* pl = (__nv_bfloat162*)(lo + i);
    ph[0] = __nv_bfloat162(h0, h1); ph[1] = __nv_bfloat162(h2, h3);
    pl[0] = __nv_bfloat162(l0, l1); pl[1] = __nv_bfloat162(l2, l3);
}

// ===========================================================================
// HMMA GEMM: D[128 x 128] = A[128 x 768] @ B[128 x 768]^T, 3-term bf16 split.
//   mode 0 (qkv): A = x split, B = {Wq,Wk,Wv} split; epilogue -> g_q/g_k/g_v
//   mode 1 (out): A = ctx split, B = Wo split; epilogue -> d_out + bo
//   256 threads = 8 warps (2m x 4n); warp tile 64x32; mma m16n8k16 bf16.
//   K chunked by 64, cp.async double buffer: 2 x (4 tiles x 16 KB) = 128 KB.
// ===========================================================================
#define KC 64
#define NKC (DMODEL / KC)            // 12
#define TB 16384                     // one 128x64 bf16 tile
#define BUF (4 * TB)                 // Ah|Al|Bh|Bl
#define GEMM_SMEM (2 * BUF)

// swizzled byte offset inside a tile for (row 0..127, c8 = col/8, col in bf16)
__device__ __forceinline__ uint32_t swz(int row, int c8) {
    return (uint32_t)(row * 128 + ((c8 ^ (row & 7)) << 4));
}

__global__ __launch_bounds__(256) void gemm_mma_kernel(
    int mode,
    const float* __restrict__ bq, const float* __restrict__ bv,
    const float* __restrict__ bo, float* __restrict__ out)
{
    extern __shared__ char smem[];
    const uint32_t sb = smem_u32(smem);
    const int tid = threadIdx.x;
    const int wid = tid >> 5;
    const int lane = tid & 31;
    const int wm = wid & 1;          // 0..1  (64 rows each)
    const int wn = wid >> 1;         // 0..3  (32 cols each)

    const int mBase = blockIdx.y * 128;
    const int nFull = blockIdx.x * 128;
    int mat, oBase;
    const __nv_bfloat16 *Ah, *Al, *Bh, *Bl;
    if (mode == 0) {
        mat = nFull / DMODEL; oBase = nFull - mat * DMODEL;
        Ah = g_x_hi; Al = g_x_lo;
        Bh = g_w_hi + (size_t)mat * DD + (size_t)oBase * DMODEL;
        Bl = g_w_lo + (size_t)mat * DD + (size_t)oBase * DMODEL;
    } else {
        mat = 3; oBase = nFull;
        Ah = g_c_hi; Al = g_c_lo;
        Bh = g_w_hi + (size_t)3 * DD + (size_t)oBase * DMODEL;
        Bl = g_w_lo + (size_t)3 * DD + (size_t)oBase * DMODEL;
    }

    float acc[4][4][4];
#pragma unroll
    for (int mt = 0; mt < 4; mt++)
#pragma unroll
        for (int nt = 0; nt < 4; nt++)
#pragma unroll
            for (int e = 0; e < 4; e++) acc[mt][nt][e] = 0.f;

    // per-thread staging slots: u = i*256+tid -> (row = u>>3, c8 = u&7)
    // issue one chunk's cp.asyncs into buffer `buf`
    auto issue = [&](int c, int buf) {
        const int k0 = c * KC;
        const uint32_t base = sb + buf * BUF;
#pragma unroll
        for (int i = 0; i < 4; i++) {
            int u = i * 256 + tid;
            int row = u >> 3;
            int c8 = u & 7;
            uint32_t so = swz(row, c8);
            int ar = mBase + row; if (ar > NTOK - 1) ar = NTOK - 1;
            size_t aoff = (size_t)ar * DMODEL + k0 + c8 * 8;
            size_t boff = (size_t)row * DMODEL + k0 + c8 * 8;
            cp16(base + 0 * TB + so, Ah + aoff);
            cp16(base + 1 * TB + so, Al + aoff);
            cp16(base + 2 * TB + so, Bh + boff);
            cp16(base + 3 * TB + so, Bl + boff);
        }
        cp_commit();
    };

    issue(0, 0);

    // ldmatrix lane address components
    const int rA = (lane & 7) + ((lane >> 3) & 1) * 8;   // row within 16
    const int cA = (lane >> 4) & 1;                      // k-chunk select
    const int rB = (lane & 7) + ((lane >> 4) & 1) * 8;   // n within 16
    const int cB = (lane >> 3) & 1;

    for (int c = 0; c < NKC; c++) {
        if (c + 1 < NKC) { issue(c + 1, (c + 1) & 1); cp_wait<1>(); }
        else             { cp_wait<0>(); }
        __syncthreads();

        const uint32_t base = sb + (c & 1) * BUF;
        const uint32_t bAh = base, bAl = base + TB, bBh = base + 2 * TB, bBl = base + 3 * TB;

#pragma unroll
        for (int ks = 0; ks < 4; ks++) {
            const int kc8 = ks * 2;
            // B fragments: 4 n8-tiles, hi & lo
            uint32_t bh[4][2], bl[4][2];
#pragma unroll
            for (int half = 0; half < 2; half++) {
                int nrow = wn * 32 + half * 16 + rB;
                uint32_t off = swz(nrow, kc8 + cB);
                ldm_x4(bh[half * 2][0], bh[half * 2][1],
                       bh[half * 2 + 1][0], bh[half * 2 + 1][1], bBh + off);
                ldm_x4(bl[half * 2][0], bl[half * 2][1],
                       bl[half * 2 + 1][0], bl[half * 2 + 1][1], bBl + off);
            }
#pragma unroll
            for (int mt = 0; mt < 4; mt++) {
                int mrow = wm * 64 + mt * 16 + rA;
                uint32_t off = swz(mrow, kc8 + cA);
                uint32_t ah[4], al[4];
                ldm_x4(ah[0], ah[1], ah[2], ah[3], bAh + off);
                ldm_x4(al[0], al[1], al[2], al[3], bAl + off);
#pragma unroll
                for (int nt = 0; nt < 4; nt++) {
                    mma_bf16(acc[mt][nt], ah, bh[nt]);
                    mma_bf16(acc[mt][nt], ah, bl[nt]);
                    mma_bf16(acc[mt][nt], al, bh[nt]);
                }
            }
        }
        __syncthreads();
    }

    // ---- epilogue ----
    const int colW = oBase + wn * 32;                 // matrix-local col base of warp
#pragma unroll
    for (int nt = 0; nt < 4; nt++) {
        const int col = colW + nt * 8 + (lane & 3) * 2;
        float b0 = 0.f, b1 = 0.f;
        if (mode == 1)      { b0 = bo[col]; b1 = bo[col + 1]; }
        else if (mat == 0)  { b0 = bq[col]; b1 = bq[col + 1]; }
        else if (mat == 2)  { b0 = bv[col]; b1 = bv[col + 1]; }
        const float scl = (mode == 0 && mat == 0) ? QSCALE : 1.0f;
#pragma unroll
        for (int mt = 0; mt < 4; mt++) {
#pragma unroll
            for (int half = 0; half < 2; half++) {
                int t = mBase + wm * 64 + mt * 16 + (lane >> 2) + half * 8;
                if (t >= NTOK) continue;
                float v0 = (acc[mt][nt][half * 2 + 0] + b0) * scl;
                float v1 = (acc[mt][nt][half * 2 + 1] + b1) * scl;
                if (mode == 0) {
                    int b_ = t / SEQ;
                    int s_ = t - b_ * SEQ;
                    int hh = col >> 6, dh = col & 63;
                    float* dst = (mat == 0) ? g_q : (mat == 1) ? g_k : g_v;
                    size_t idx = (((size_t)b_ * NHEAD + hh) * SEQ + s_) * DHEAD + dh;
                    *(float2*)&dst[idx] = make_float2(v0, v1);
                } else {
                    *(float2*)&out[(size_t)t * DMODEL + col] = make_float2(v0, v1);
                }
            }
        }
    }
}

// ===========================================================================
// Flash attention, fp32 FMA2; epilogue emits ctx bf16 hi/lo.
// ===========================================================================
__global__ __launch_bounds__(256) void attn_kernel()
{
    __shared__ __align__(16) float Qt[64][64];   // [d][m]
    __shared__ __align__(16) float KP[64][64];   // [d][n] for K^T, then [m][j] for P
    __shared__ __align__(16) float Vs[64][64];   // [j][d]

    const int tid = threadIdx.x;
    const int tx = tid & 15;
    const int ty = tid >> 4;
    const int bh = blockIdx.y;
    const int b_ = bh / NHEAD;
    const int h_ = bh - b_ * NHEAD;
    const int q0 = blockIdx.x * 64;

    const float* Qg = g_q + (size_t)bh * SEQ * DHEAD;
    const float* Kg = g_k + (size_t)bh * SEQ * DHEAD;
    const float* Vg = g_v + (size_t)bh * SEQ * DHEAD;

    const int ldRow = tid >> 2;
    const int ldC0  = (tid & 3) * 4;

    {
        int qr = q0 + ldRow;
        const float* qp = Qg + (size_t)qr * DHEAD;
#pragma unroll
        for (int p = 0; p < 4; p++) {
            int c = ldC0 + p * 16;
            float4 qv = (qr < SEQ) ? *(const float4*)(qp + c) : make_float4(0, 0, 0, 0);
            Qt[c + 0][ldRow] = qv.x; Qt[c + 1][ldRow] = qv.y;
            Qt[c + 2][ldRow] = qv.z; Qt[c + 3][ldRow] = qv.w;
        }
    }

    ull O2[4][2];
#pragma unroll
    for (int i = 0; i < 4; i++) { O2[i][0] = 0ull; O2[i][1] = 0ull; }
    float mrow[4] = {NEG_BIG, NEG_BIG, NEG_BIG, NEG_BIG};
    float lrow[4] = {0.f, 0.f, 0.f, 0.f};

    const int NKT = (SEQ + 63) / 64;
    for (int kt = 0; kt < NKT; kt++) {
        const int kBase = kt * 64;

        float4 kfr[4], vfr[4];
        {
            int kr = kBase + ldRow;
            bool ok = kr < SEQ;
            const float* kp = Kg + (size_t)kr * DHEAD;
            const float* vp = Vg + (size_t)kr * DHEAD;
#pragma unroll
            for (int p = 0; p < 4; p++) {
                int c = ldC0 + p * 16;
                kfr[p] = ok ? *(const float4*)(kp + c) : make_float4(0, 0, 0, 0);
                vfr[p] = ok ? *(const float4*)(vp + c) : make_float4(0, 0, 0, 0);
            }
        }
        __syncthreads();
#pragma unroll
        for (int p = 0; p < 4; p++) {
            int c = ldC0 + p * 16;
            KP[c + 0][ldRow] = kfr[p].x; KP[c + 1][ldRow] = kfr[p].y;
            KP[c + 2][ldRow] = kfr[p].z; KP[c + 3][ldRow] = kfr[p].w;
            *(float4*)&Vs[ldRow][c] = vfr[p];
        }
        __syncthreads();

        ull s2[4][2];
#pragma unroll
        for (int i = 0; i < 4; i++) { s2[i][0] = 0ull; s2[i][1] = 0ull; }
#pragma unroll 16
        for (int d = 0; d < DHEAD; d++) {
            float4 af = *(const float4*)&Qt[d][ty * 4];
            ulonglong2 bu = *(const ulonglong2*)&KP[d][tx * 4];
            ull a0 = dup2(af.x), a1 = dup2(af.y), a2 = dup2(af.z), a3 = dup2(af.w);
            fma2(s2[0][0], a0, bu.x); fma2(s2[0][1], a0, bu.y);
            fma2(s2[1][0], a1, bu.x); fma2(s2[1][1], a1, bu.y);
            fma2(s2[2][0], a2, bu.x); fma2(s2[2][1], a2, bu.y);
            fma2(s2[3][0], a3, bu.x); fma2(s2[3][1], a3, bu.y);
        }

        float s[4][4];
#pragma unroll
        for (int i = 0; i < 4; i++) {
            float2 lo = unpk(s2[i][0]);
            float2 hi = unpk(s2[i][1]);
            s[i][0] = lo.x; s[i][1] = lo.y; s[i][2] = hi.x; s[i][3] = hi.y;
        }

#pragma unroll
        for (int j = 0; j < 4; j++) {
            if (kBase + tx * 4 + j >= SEQ) {
#pragma unroll
                for (int i = 0; i < 4; i++) s[i][j] = NEG_BIG;
            }
        }

#pragma unroll
        for (int i = 0; i < 4; i++) {
            float mx = fmaxf(fmaxf(s[i][0], s[i][1]), fmaxf(s[i][2], s[i][3]));
            mx = fmaxf(mx, __shfl_xor_sync(0xffffffffu, mx, 1));
            mx = fmaxf(mx, __shfl_xor_sync(0xffffffffu, mx, 2));
            mx = fmaxf(mx, __shfl_xor_sync(0xffffffffu, mx, 4));
            mx = fmaxf(mx, __shfl_xor_sync(0xffffffffu, mx, 8));
            float mnew = fmaxf(mrow[i], mx);
            float alpha = __expf(mrow[i] - mnew);
            mrow[i] = mnew;
            float rs = 0.f;
#pragma unroll
            for (int j = 0; j < 4; j++) {
                s[i][j] = __expf(s[i][j] - mnew);
                rs += s[i][j];
            }
            rs += __shfl_xor_sync(0xffffffffu, rs, 1);
            rs += __shfl_xor_sync(0xffffffffu, rs, 2);
            rs += __shfl_xor_sync(0xffffffffu, rs, 4);
            rs += __shfl_xor_sync(0xffffffffu, rs, 8);
            lrow[i] = lrow[i] * alpha + rs;
            ull ad = dup2(alpha);
            mul2(O2[i][0], ad); mul2(O2[i][1], ad);
        }

        __syncthreads();
#pragma unroll
        for (int i = 0; i < 4; i++) {
            *(float4*)&KP[ty * 4 + i][tx * 4] =
                make_float4(s[i][0], s[i][1], s[i][2], s[i][3]);
        }
        __syncthreads();

#pragma unroll 4
        for (int j = 0; j < 64; j += 4) {
            ulonglong2 v0 = *(const ulonglong2*)&Vs[j + 0][tx * 4];
            ulonglong2 v1 = *(const ulonglong2*)&Vs[j + 1][tx * 4];
            ulonglong2 v2 = *(const ulonglong2*)&Vs[j + 2][tx * 4];
            ulonglong2 v3 = *(const ulonglong2*)&Vs[j + 3][tx * 4];
#pragma unroll
            for (int i = 0; i < 4; i++) {
                float4 pf = *(const float4*)&KP[ty * 4 + i][j];
                ull p0 = dup2(pf.x), p1 = dup2(pf.y), p2 = dup2(pf.z), p3 = dup2(pf.w);
                fma2(O2[i][0], p0, v0.x); fma2(O2[i][1], p0, v0.y);
                fma2(O2[i][0], p1, v1.x); fma2(O2[i][1], p1, v1.y);
                fma2(O2[i][0], p2, v2.x); fma2(O2[i][1], p2, v2.y);
                fma2(O2[i][0], p3, v3.x); fma2(O2[i][1], p3, v3.y);
            }
        }
    }

    // ---- finalize: ctx -> bf16 hi/lo split ----
#pragma unroll
    for (int i = 0; i < 4; i++) {
        int qr = q0 + ty * 4 + i;
        if (qr >= SEQ) continue;
        float inv = 1.f / lrow[i];
        float2 lo2 = unpk(O2[i][0]);
        float2 hi2 = unpk(O2[i][1]);
        float vals[4] = {lo2.x * inv, lo2.y * inv, hi2.x * inv, hi2.y * inv};
        size_t idx = ((size_t)b_ * SEQ + qr) * DMODEL + h_ * DHEAD + tx * 4;
        __nv_bfloat16 h[4], l[4];
#pragma unroll
        for (int j = 0; j < 4; j++) {
            h[j] = __float2bfloat16(vals[j]);
            l[j] = __float2bfloat16(vals[j] - __bfloat162float(h[j]));
        }
        __nv_bfloat162* ph = (__nv_bfloat162*)&g_c_hi[idx];
        __nv_bfloat162* pl = (__nv_bfloat162*)&g_c_lo[idx];
        ph[0] = __nv_bfloat162(h[0], h[1]); ph[1] = __nv_bfloat162(h[2], h[3]);
        pl[0] = __nv_bfloat162(l[0], l[1]); pl[1] = __nv_bfloat162(l[2], l[3]);
    }
}

// ===========================================================================
extern "C" void kernel_launch(void* const* d_in, const int* in_sizes, int n_in,
                              void* d_out, int out_size)
{
    const float* x  = (const float*)d_in[0];
    const float* Wq = (const float*)d_in[1];
    const float* bq = (const float*)d_in[2];
    const float* Wk = (const float*)d_in[3];
    const float* Wv = (const float*)d_in[4];
    const float* bv = (const float*)d_in[5];
    const float* Wo = (const float*)d_in[6];
    const float* bo = (const float*)d_in[7];
    float* out = (float*)d_out;

    cudaFuncSetAttribute(gemm_mma_kernel,
                         cudaFuncAttributeMaxDynamicSharedMemorySize, GEMM_SMEM);

    // split inputs to bf16 hi/lo
    cvt_kernel<<<(NTOK * DMODEL) / 1024, 256>>>(x, 0, NTOK * DMODEL);
    cvt_kernel<<<DD / 1024, 256>>>(Wq, 1, DD);
    cvt_kernel<<<DD / 1024, 256>>>(Wk, 2, DD);
    cvt_kernel<<<DD / 1024, 256>>>(Wv, 3, DD);
    cvt_kernel<<<DD / 1024, 256>>>(Wo, 4, DD);

    // QKV projection on tensor cores (HMMA)
    dim3 gQKV(3 * DMODEL / 128, (NTOK + 127) / 128);   // (18, 94)
    gemm_mma_kernel<<<gQKV, 256, GEMM_SMEM>>>(0, bq, bv, bo, out);

    // flash attention (writes ctx split)
    dim3 gAtt((SEQ + 63) / 64, BATCH * NHEAD);          // (24, 96)
    attn_kernel<<<gAtt, 256>>>();

    // output projection on tensor cores (HMMA)
    dim3 gOut(DMODEL / 128, (NTOK + 127) / 128);        // (6, 94)
    gemm_mma_kernel<<<gOut, 256, GEMM_SMEM>>>(1, bq, bv, bo, out);
}